// round 17
// baseline (speedup 1.0000x reference)
#include <cuda_runtime.h>

#define NCLS 32
#define SOSC 30
#define EOSC 31
#define LOG2E 1.4426950408889634f
#define LN2F  0.6931471805599453f
#define MAXB  8192

typedef unsigned long long u64;

__device__ float g_vec[2][MAXB][NCLS];   // [dir][batch][class] scan results
__device__ int   g_eC[2][MAXB];          // [dir][batch] exact log2 offsets

__device__ __forceinline__ float ex2f(float x){ float r; asm("ex2.approx.f32 %0, %1;" : "=f"(r) : "f"(x)); return r; }
__device__ __forceinline__ float lg2f_(float x){ float r; asm("lg2.approx.f32 %0, %1;" : "=f"(r) : "f"(x)); return r; }
__device__ __forceinline__ u64 pk2(float lo, float hi){ u64 r; asm("mov.b64 %0, {%1,%2};" : "=l"(r) : "f"(lo), "f"(hi)); return r; }
__device__ __forceinline__ void up2(u64 v, float& lo, float& hi){ asm("mov.b64 {%0,%1}, %2;" : "=f"(lo), "=f"(hi) : "l"(v)); }
__device__ __forceinline__ u64 ffma2(u64 a, u64 b, u64 c){ u64 d; asm("fma.rn.f32x2 %0, %1, %2, %3;" : "=l"(d) : "l"(a), "l"(b), "l"(c)); return d; }
__device__ __forceinline__ u64 fadd2(u64 a, u64 b){ u64 d; asm("add.rn.f32x2 %0, %1, %2;" : "=l"(d) : "l"(a), "l"(b)); return d; }
__device__ __forceinline__ u64 fmul2(u64 a, u64 b){ u64 d; asm("mul.rn.f32x2 %0, %1, %2;" : "=l"(d) : "l"(a), "l"(b)); return d; }
__device__ __forceinline__ u64 fsub2(u64 a, u64 b){ u64 d; asm("sub.rn.f32x2 %0, %1, %2;" : "=l"(d) : "l"(a), "l"(b)); return d; }

// Exact power-of-2 rescale factor from a stale probe value d (pure ALU).
__device__ __forceinline__ float po2_rescale(float d, int& eacc){
    unsigned u = __float_as_uint(d);
    int e = (int)(u >> 23) & 0xff;
    if (e == 0 || e >= 254) return 1.0f;
    eacc += (e - 127);
    return __uint_as_float((unsigned)(254 - e) << 23);
}

// One half-scan, direction fixed at compile time. Layout (MIO-minimal):
// warp = 4 batches; 8 lanes/batch; lane owns 4 classes, FULL k=32 dots.
// Exchange software-pipelined: at end of step t, store P(t+1), syncwarp,
// and load q(t+1) into registers — LDS latency overlaps the fe prefetch
// and bookkeeping instead of stalling the next dot.
// DIRB=0: P' = m * fe o (E q) + (1-m) P       (store P)
// DIRB=1: u' = m * E^T(exchange(u o fe)) + (1-m) u  (store u o fe; E2 = E^T)
// Numerics: exp-domain, blend-then-po2-rescale every 4 steps, stale pivot.
template<int DIRB>
__device__ __forceinline__ void scan_body(
    const u64 E2[4][16], u64 P2[2], int& eC,
    const float* fbase, const float* mbase,
    unsigned fstep, unsigned mstep,
    int n, int tbeg, int dt, int lane,
    float* stbase, const float* ldbase, int dstride)
{
    if (n <= 0) return;
    const int tlast = tbeg + dt * (n - 1);

    // 2-deep prefetch of exp(feat) (4 classes/lane) and scalar mask.
    u64 fe[2][2]; float mk[2];
#pragma unroll
    for (int j = 0; j < 2; ++j){
        int tc = (j < n) ? (tbeg + dt * j) : tlast;
        float4 f4 = *reinterpret_cast<const float4*>(fbase + (size_t)((unsigned)tc * fstep));
        fe[j][0] = pk2(ex2f(f4.x*LOG2E), ex2f(f4.y*LOG2E));
        fe[j][1] = pk2(ex2f(f4.z*LOG2E), ex2f(f4.w*LOG2E));
        mk[j] = mbase[(unsigned)tc * mstep];
    }

    // prologue: publish state entering step 0 into buffer 0, preload q
    {
        u64 s0 = P2[0], s1 = P2[1];
        if (DIRB != 0){ s0 = fmul2(s0, fe[0][0]); s1 = fmul2(s1, fe[0][1]); }
        ulonglong2 v; v.x = s0; v.y = s1;
        *reinterpret_cast<ulonglong2*>(stbase) = v;
        __syncwarp();
    }
    u64 q[16];
#pragma unroll
    for (int si = 0; si < 8; ++si){
        ulonglong2 v = *reinterpret_cast<const ulonglong2*>(ldbase + si * 4);
        q[2*si] = v.x; q[2*si+1] = v.y;
    }

    int done = 0;
    for (; done + 2 <= n; done += 2){
#pragma unroll
        for (int j = 0; j < 2; ++j){
            // stale rescale pivot every 4 steps (ALU+shfl, overlaps dot)
            float r = 1.0f;
            const bool dopiv = (j == 0) && ((done & 3) == 0);
            if (dopiv){
                float plo, phi; up2(P2[0], plo, phi);
                float piv = __shfl_sync(0xffffffffu, plo, lane & 24);
                r = po2_rescale(piv, eC);
            }
            // full 32-k dots for this lane's 4 classes (q already live)
            u64 aA[4], aB[4];
#pragma unroll
            for (int ci = 0; ci < 4; ++ci){
                aA[ci] = ffma2(E2[ci][0], q[0], 0ull);
                aB[ci] = ffma2(E2[ci][1], q[1], 0ull);
            }
#pragma unroll
            for (int kp = 2; kp < 16; kp += 2){
#pragma unroll
                for (int ci = 0; ci < 4; ++ci){
                    aA[ci] = ffma2(E2[ci][kp],   q[kp],   aA[ci]);
                    aB[ci] = ffma2(E2[ci][kp+1], q[kp+1], aB[ci]);
                }
            }
            float s[4];
#pragma unroll
            for (int ci = 0; ci < 4; ++ci){
                u64 a = fadd2(aA[ci], aB[ci]);
                float lo, hi; up2(a, lo, hi);
                s[ci] = lo + hi;
            }
            u64 Pn0, Pn1;
            if (DIRB == 0){
                Pn0 = fmul2(pk2(s[0], s[1]), fe[j][0]);
                Pn1 = fmul2(pk2(s[2], s[3]), fe[j][1]);
            } else {
                Pn0 = pk2(s[0], s[1]);
                Pn1 = pk2(s[2], s[3]);
            }
            // arithmetic blend (operands share one scale; exact for m in {0,1})
            u64 mm = pk2(mk[j], mk[j]);
            P2[0] = ffma2(mm, fsub2(Pn0, P2[0]), P2[0]);
            P2[1] = ffma2(mm, fsub2(Pn1, P2[1]), P2[1]);
            if (dopiv){
                u64 rr = pk2(r, r);
                P2[0] = fmul2(P2[0], rr);
                P2[1] = fmul2(P2[1], rr);
            }
            // pipelined exchange for the NEXT step: store, sync, preload q
            {
                u64 s0 = P2[0], s1 = P2[1];
                if (DIRB != 0){
                    s0 = fmul2(s0, fe[(j+1)&1][0]);   // fe of step done+j+1
                    s1 = fmul2(s1, fe[(j+1)&1][1]);
                }
                ulonglong2 v; v.x = s0; v.y = s1;
                *reinterpret_cast<ulonglong2*>(stbase + ((j+1)&1) * dstride) = v;
                __syncwarp();
                const float* ld = ldbase + ((j+1)&1) * dstride;
#pragma unroll
                for (int si = 0; si < 8; ++si){
                    ulonglong2 w = *reinterpret_cast<const ulonglong2*>(ld + si * 4);
                    q[2*si] = w.x; q[2*si+1] = w.y;
                }
            }
            // prefetch fe[j] <- step done+2+j (clamped; fe[j] fully consumed)
            {
                int sn = done + 2 + j;
                int tc = (sn < n) ? (tbeg + dt * sn) : tlast;
                float4 f4 = *reinterpret_cast<const float4*>(fbase + (size_t)((unsigned)tc * fstep));
                fe[j][0] = pk2(ex2f(f4.x*LOG2E), ex2f(f4.y*LOG2E));
                fe[j][1] = pk2(ex2f(f4.z*LOG2E), ex2f(f4.w*LOG2E));
                mk[j] = mbase[(unsigned)tc * mstep];
            }
        }
    }
    // tail (n odd; not hit for seq=512/mid=256). Non-pipelined, self-contained.
    for (; done < n; ++done){
        int t = tbeg + dt * done;
        float4 f4 = *reinterpret_cast<const float4*>(fbase + (size_t)((unsigned)t * fstep));
        u64 fe0 = pk2(ex2f(f4.x*LOG2E), ex2f(f4.y*LOG2E));
        u64 fe1 = pk2(ex2f(f4.z*LOG2E), ex2f(f4.w*LOG2E));
        float m = mbase[(unsigned)t * mstep];
        u64 mv = pk2(m, m);
        u64 s0 = P2[0], s1 = P2[1];
        if (DIRB != 0){ s0 = fmul2(s0, fe0); s1 = fmul2(s1, fe1); }
        {
            ulonglong2 v; v.x = s0; v.y = s1;
            *reinterpret_cast<ulonglong2*>(stbase) = v;
        }
        __syncwarp();
#pragma unroll
        for (int si = 0; si < 8; ++si){
            ulonglong2 v = *reinterpret_cast<const ulonglong2*>(ldbase + si * 4);
            q[2*si] = v.x; q[2*si+1] = v.y;
        }
        float s[4];
#pragma unroll
        for (int ci = 0; ci < 4; ++ci){
            u64 aA = 0ull, aB = 0ull;
#pragma unroll
            for (int kp = 0; kp < 16; kp += 2){
                aA = ffma2(E2[ci][kp],   q[kp],   aA);
                aB = ffma2(E2[ci][kp+1], q[kp+1], aB);
            }
            u64 a = fadd2(aA, aB);
            float lo, hi; up2(a, lo, hi);
            s[ci] = lo + hi;
        }
        u64 Pn0, Pn1;
        if (DIRB == 0){ Pn0 = fmul2(pk2(s[0], s[1]), fe0); Pn1 = fmul2(pk2(s[2], s[3]), fe1); }
        else          { Pn0 = pk2(s[0], s[1]);             Pn1 = pk2(s[2], s[3]); }
        P2[0] = ffma2(mv, fsub2(Pn0, P2[0]), P2[0]);
        P2[1] = ffma2(mv, fsub2(Pn1, P2[1]), P2[1]);
        {
            float plo, phi; up2(P2[0], plo, phi);
            float piv = __shfl_sync(0xffffffffu, plo, lane & 24);
            float r = po2_rescale(piv, eC);
            u64 rr = pk2(r, r);
            P2[0] = fmul2(P2[0], rr);
            P2[1] = fmul2(P2[1], rr);
        }
        __syncwarp();
    }
}

// Bidirectional exp-domain CRF scan. CTA = 1 warp = 4 batches x 1 direction.
// Grid = 2*ceil(batch/4) one-warp CTAs -> near-perfect SM balance (1024/148).
__global__ __launch_bounds__(32, 7)
void crf_scan(const float* __restrict__ feats,
              const float* __restrict__ mask,
              const float* __restrict__ trans,
              int seq, int batch, int mid)
{
    __shared__ __align__(16) float pbuf[2][4][36];  // [dbl][batch][36]
    const int lane = threadIdx.x & 31;
    const int b    = lane >> 3;       // batch slot in warp (0..3)
    const int g    = lane & 7;        // class group -> classes 4g..4g+3
    const int c0   = g * 4;
    const int dirb = blockIdx.x & 1;  // 0 = forward, 1 = backward
    const int quad = blockIdx.x >> 1;
    int bb = quad * 4 + b;
    const bool real = (bb < batch);
    if (!real) bb = batch - 1;

    // E2: fwd = rows of exp(T); bwd = rows of exp(T)^T. 4 classes x 16 kp.
    u64 E2[4][16];
    if (dirb == 0){
#pragma unroll
        for (int ci = 0; ci < 4; ++ci){
            const float* tr = trans + (c0 + ci) * NCLS;
#pragma unroll
            for (int kp = 0; kp < 16; ++kp)
                E2[ci][kp] = pk2(ex2f(tr[2*kp] * LOG2E), ex2f(tr[2*kp+1] * LOG2E));
        }
    } else {
#pragma unroll
        for (int ci = 0; ci < 4; ++ci){
#pragma unroll
            for (int kp = 0; kp < 16; ++kp)
                E2[ci][kp] = pk2(ex2f(trans[(2*kp    ) * NCLS + c0 + ci] * LOG2E),
                                 ex2f(trans[(2*kp + 1) * NCLS + c0 + ci] * LOG2E));
        }
    }

    u64 P2[2];
    if (dirb == 0){
        P2[0] = pk2((c0+0==SOSC)?1.f:0.f, (c0+1==SOSC)?1.f:0.f);
        P2[1] = pk2((c0+2==SOSC)?1.f:0.f, (c0+3==SOSC)?1.f:0.f);
    } else {
        const float* te = trans + EOSC * NCLS + c0;
        P2[0] = pk2(ex2f(te[0]*LOG2E), ex2f(te[1]*LOG2E));
        P2[1] = pk2(ex2f(te[2]*LOG2E), ex2f(te[3]*LOG2E));
    }
    int eC = 0;

    const float* fbase = feats + (size_t)bb * NCLS + c0;
    const float* mbase = mask + bb;
    const unsigned fstep = (unsigned)batch * NCLS;
    const unsigned mstep = (unsigned)batch;

    float* const stbase = &pbuf[0][b][c0];
    const float* const ldbase = &pbuf[0][b][0];
    const int dstride = 4 * 36;

    if (dirb == 0)
        scan_body<0>(E2, P2, eC, fbase, mbase, fstep, mstep,
                     mid, 0, 1, lane, stbase, ldbase, dstride);
    else
        scan_body<1>(E2, P2, eC, fbase, mbase, fstep, mstep,
                     seq - mid, seq - 1, -1, lane, stbase, ldbase, dstride);

    // Publish half-scan result: each lane stores its 4 classes.
    if (real){
        float a0, a1, a2, a3;
        up2(P2[0], a0, a1); up2(P2[1], a2, a3);
        float4 w; w.x = a0; w.y = a1; w.z = a2; w.w = a3;
        *reinterpret_cast<float4*>(&g_vec[dirb][bb][c0]) = w;
        if (g == 0) g_eC[dirb][bb] = eC;
    }
}

// out[b] = ln2 * (eC_f + eC_b + log2( sum_c P_mid[c] * u_mid[c] ))
__global__ void crf_combine(float* __restrict__ out, int batch)
{
    const int w = threadIdx.x >> 5;
    const int lane = threadIdx.x & 31;
    const int bb = blockIdx.x * 8 + w;
    if (bb >= batch) return;
    float v = g_vec[0][bb][lane] * g_vec[1][bb][lane];
#pragma unroll
    for (int off = 16; off > 0; off >>= 1)
        v += __shfl_xor_sync(0xffffffffu, v, off);
    if (lane == 0)
        out[bb] = ((float)(g_eC[0][bb] + g_eC[1][bb]) + lg2f_(v)) * LN2F;
}

extern "C" void kernel_launch(void* const* d_in, const int* in_sizes, int n_in,
                              void* d_out, int out_size)
{
    const float* feats = (const float*)d_in[0];
    const float* mask  = (const float*)d_in[1];
    const float* trans = (const float*)d_in[2];
    float* out = (float*)d_out;

    const int batch = out_size;                 // out is (batch,)
    const int seq   = in_sizes[1] / batch;      // mask is (seq, batch)
    const int mid   = seq / 2;

    const int nquads = (batch + 3) / 4;         // warp = 4 batches x 1 dir
    crf_scan<<<nquads * 2, 32>>>(feats, mask, trans, seq, batch, mid);
    crf_combine<<<(batch + 7) / 8, 256>>>(out, batch);
}